// round 15
// baseline (speedup 1.0000x reference)
#include <cuda_runtime.h>
#include <cuda_fp16.h>
#include <cstdint>

#define DM 1024     // d_model
#define NH 16       // heads
#define DH 64       // head dim
#define BB 4        // batch
#define SS 1024     // seq
#define MT (BB*SS)  // 4096 rows

#define ATS ((DM/2)*MT)   // half2 per activation slot
#define WTS ((DM/2)*DM)   // half2 per weight slot

// ---------------- scratch ----------------
__device__ __half2 g_acts[3*ATS];    // conv'd activations: gfeat, lfeat, tfeat
__device__ __half2 g_wts[7*WTS];     // conv'd weights: gq,gk,gv,pq,pk,pv,dense
__device__ __half  g_proj[6*(size_t)MT*DM];  // qh,kh,vh,pqh,pkh,pvh
__device__ __half  g_a2h[(size_t)MT*DM];     // att2 + gv
__device__ __half2 g_ctxat[ATS];     // ctx in permuted at-layout (attn#2 output)

struct Ptrs7 { const float* p[7]; };
struct Ptrs3 { const float* p[3]; };
struct Bias3 { const float* p[3]; };

__device__ __forceinline__ void mma16(float* c,
    uint32_t a0, uint32_t a1, uint32_t a2, uint32_t a3, uint32_t b0, uint32_t b1) {
    asm volatile(
        "mma.sync.aligned.m16n8k16.row.col.f32.f16.f16.f32 "
        "{%0,%1,%2,%3},{%4,%5,%6,%7},{%8,%9},{%0,%1,%2,%3};\n"
        : "+f"(c[0]), "+f"(c[1]), "+f"(c[2]), "+f"(c[3])
        : "r"(a0), "r"(a1), "r"(a2), "r"(a3), "r"(b0), "r"(b1));
}
__device__ __forceinline__ uint32_t smem_u32(const void* p) {
    uint32_t a;
    asm("{ .reg .u64 t; cvta.to.shared.u64 t, %1; cvt.u32.u64 %0, t; }" : "=r"(a) : "l"(p));
    return a;
}
__device__ __forceinline__ void cp16(uint32_t dst, const void* src) {
    asm volatile("cp.async.cg.shared.global [%0], [%1], 16;" :: "r"(dst), "l"(src) : "memory");
}
__device__ __forceinline__ uint32_t packh2(float lo, float hi) {
    uint32_t r;
    asm("cvt.rn.f16x2.f32 %0, %1, %2;" : "=r"(r) : "f"(hi), "f"(lo));
    return r;
}
__device__ __forceinline__ uint32_t prmt(uint32_t a, uint32_t b, uint32_t s) {
    uint32_t d;
    asm("prmt.b32 %0, %1, %2, %3;" : "=r"(d) : "r"(a), "r"(b), "r"(s));
    return d;
}

// ---------------- batched converts: fp32 -> half2 transposed+permuted+k-packed --
__device__ __forceinline__ void conv_body(
    const float* __restrict__ in, __half2* __restrict__ out, int Rm, int isW)
{
    __shared__ float ts[128][33];
    const int m0 = blockIdx.x << 7, k0 = blockIdx.y << 5;
#pragma unroll
    for (int i = 0; i < 4; i++) {
        int idx = threadIdx.x + (i << 8);
        int ml = idx >> 3, kc = (idx & 7) << 2;
        float4 v = *(const float4*)(in + (size_t)(m0 + ml) * 1024 + k0 + kc);
        ts[ml][kc] = v.x; ts[ml][kc+1] = v.y; ts[ml][kc+2] = v.z; ts[ml][kc+3] = v.w;
    }
    __syncthreads();
#pragma unroll
    for (int i = 0; i < 8; i++) {
        int idx = threadIdx.x + (i << 8);      // 0..2047
        int kp = idx >> 7, sc = idx & 127;
        int ml;
        if (isW) {
            int ch = sc >> 5, r = sc & 31, gg = (r >> 2) & 7, nt = r & 3;
            ml = ch * 32 + nt * 8 + gg;
        } else {
            int hf = sc >> 6, r = sc & 63, hi = (r >> 5) & 1, gg = (r >> 2) & 7, mt = r & 3;
            ml = hf * 64 + mt * 16 + hi * 8 + gg;
        }
        out[(size_t)((k0 >> 1) + kp) * Rm + m0 + sc] =
            __floats2half2_rn(ts[ml][2*kp], ts[ml][2*kp+1]);
    }
}
__global__ __launch_bounds__(256) void conv_w_all(Ptrs7 srcs, __half2* __restrict__ out) {
    conv_body(srcs.p[blockIdx.z], out + (size_t)blockIdx.z * WTS, DM, 1);
}
__global__ __launch_bounds__(256) void conv_a_all(Ptrs3 srcs, __half2* __restrict__ out) {
    conv_body(srcs.p[blockIdx.z], out + (size_t)blockIdx.z * ATS, MT, 0);
}

// ---------------- GEMM fp16 (unchanged proven shape) ----------------------------
#define LDH 136
#define STG_H2 (32*LDH)
#define STG_BY (STG_H2*4)     // 17408 bytes
#define GSMEM (3*2*STG_BY)    // 104448

__global__ __launch_bounds__(128, 2) void gemm_fp16(
    const __half2* __restrict__ At, const __half2* __restrict__ Wt,
    const float* __restrict__ bias, float* __restrict__ Cf, __half* __restrict__ Ch)
{
    extern __shared__ __half2 smh[];
    const uint32_t sb = smem_u32(smh);
    const int tid = threadIdx.x, wid = tid >> 5, lane = tid & 31;
    const int g = lane >> 2, tig = lane & 3;
    const int wmh = (wid >> 1) * 64;
    const int wnc = (wid & 1) * 64;
    const int bm = blockIdx.y << 7, bn = blockIdx.x << 7;

    float acc[4][8][4];
#pragma unroll
    for (int i = 0; i < 4; i++)
#pragma unroll
        for (int j = 0; j < 8; j++)
#pragma unroll
            for (int e = 0; e < 4; e++) acc[i][j][e] = 0.f;

#define LOAD_STAGE(J, S) do { \
    uint32_t dst = sb + (uint32_t)(S) * 2 * STG_BY; \
    _Pragma("unroll") \
    for (int p = 0; p < 8; p++) { \
        int ci = tid + (p << 7); \
        int row = ci >> 5, cc = ci & 31; \
        cp16(dst + row * (LDH*4) + cc * 16, \
             At + (size_t)((J) * 32 + row) * MT + bm + cc * 4); \
        cp16(dst + STG_BY + row * (LDH*4) + cc * 16, \
             Wt + (size_t)((J) * 32 + row) * DM + bn + cc * 4); \
    } \
    asm volatile("cp.async.commit_group;" ::: "memory"); \
} while (0)

    LOAD_STAGE(0, 0);
    LOAD_STAGE(1, 1);

    for (int j = 0; j < 16; j++) {
        if (j < 15) asm volatile("cp.async.wait_group 1;" ::: "memory");
        else        asm volatile("cp.async.wait_group 0;" ::: "memory");
        __syncthreads();

        const __half2* Ab = smh + (j % 3) * 2 * STG_H2;
        const __half2* Wb = Ab + STG_H2;
#pragma unroll
        for (int ks = 0; ks < 4; ks++) {
            const int kp0 = ks * 8 + tig;
            uint4 ua0 = *(const uint4*)&Ab[kp0*LDH     + wmh      + g*4];
            uint4 ua1 = *(const uint4*)&Ab[kp0*LDH     + wmh + 32 + g*4];
            uint4 ua2 = *(const uint4*)&Ab[(kp0+4)*LDH + wmh      + g*4];
            uint4 ua3 = *(const uint4*)&Ab[(kp0+4)*LDH + wmh + 32 + g*4];
            uint4 ub00 = *(const uint4*)&Wb[kp0*LDH     + wnc      + g*4];
            uint4 ub01 = *(const uint4*)&Wb[kp0*LDH     + wnc + 32 + g*4];
            uint4 ub10 = *(const uint4*)&Wb[(kp0+4)*LDH + wnc      + g*4];
            uint4 ub11 = *(const uint4*)&Wb[(kp0+4)*LDH + wnc + 32 + g*4];
            const uint32_t a0[4] = {ua0.x, ua0.y, ua0.z, ua0.w};
            const uint32_t a1[4] = {ua1.x, ua1.y, ua1.z, ua1.w};
            const uint32_t a2[4] = {ua2.x, ua2.y, ua2.z, ua2.w};
            const uint32_t a3[4] = {ua3.x, ua3.y, ua3.z, ua3.w};
            const uint32_t b0[8] = {ub00.x,ub00.y,ub00.z,ub00.w, ub01.x,ub01.y,ub01.z,ub01.w};
            const uint32_t b1[8] = {ub10.x,ub10.y,ub10.z,ub10.w, ub11.x,ub11.y,ub11.z,ub11.w};
#pragma unroll
            for (int mt = 0; mt < 4; mt++)
#pragma unroll
                for (int nt = 0; nt < 8; nt++)
                    mma16(acc[mt][nt], a0[mt], a1[mt], a2[mt], a3[mt],
                          b0[nt], b1[nt]);
        }
        if (j + 2 < 16) LOAD_STAGE(j + 2, (j + 2) % 3);
    }
#undef LOAD_STAGE

#pragma unroll
    for (int mt = 0; mt < 4; mt++) {
        int r0 = bm + (wid >> 1) * 64 + mt * 16 + g;
#pragma unroll
        for (int nt = 0; nt < 8; nt++) {
            int c = bn + (wid & 1) * 64 + (nt >> 2) * 32 + (nt & 3) * 8 + 2 * tig;
            float2 bv = *(const float2*)(bias + c);
            float o00 = acc[mt][nt][0] + bv.x, o01 = acc[mt][nt][1] + bv.y;
            float o10 = acc[mt][nt][2] + bv.x, o11 = acc[mt][nt][3] + bv.y;
            if (Ch) {
                *(uint32_t*)&Ch[(size_t)r0 * DM + c]       = packh2(o00, o01);
                *(uint32_t*)&Ch[(size_t)(r0 + 8) * DM + c] = packh2(o10, o11);
            } else {
                *(float2*)(Cf + (size_t)r0 * DM + c)       = make_float2(o00, o01);
                *(float2*)(Cf + (size_t)(r0 + 8) * DM + c) = make_float2(o10, o11);
            }
        }
    }
}

// ---------------- multi-slot GEMM: slot folded into blockIdx.x (wave packing) --
// blockIdx.x in [0, 8*nslots): slot = x>>3 selects weight slot / bias / dst.
__global__ __launch_bounds__(128, 2) void gemm_multi(
    const __half2* __restrict__ At, const __half2* __restrict__ Wts,
    Bias3 biases, __half* __restrict__ dstBase)
{
    extern __shared__ __half2 smh[];
    const uint32_t sb = smem_u32(smh);
    const int slot = blockIdx.x >> 3;
    const __half2* Wt = Wts + (size_t)slot * WTS;
    const float* bias = biases.p[slot];
    __half* Ch = dstBase + (size_t)slot * MT * DM;

    const int tid = threadIdx.x, wid = tid >> 5, lane = tid & 31;
    const int g = lane >> 2, tig = lane & 3;
    const int wmh = (wid >> 1) * 64;
    const int wnc = (wid & 1) * 64;
    const int bm = blockIdx.y << 7, bn = (blockIdx.x & 7) << 7;

    float acc[4][8][4];
#pragma unroll
    for (int i = 0; i < 4; i++)
#pragma unroll
        for (int j = 0; j < 8; j++)
#pragma unroll
            for (int e = 0; e < 4; e++) acc[i][j][e] = 0.f;

#define LOAD_STAGE(J, S) do { \
    uint32_t dst = sb + (uint32_t)(S) * 2 * STG_BY; \
    _Pragma("unroll") \
    for (int p = 0; p < 8; p++) { \
        int ci = tid + (p << 7); \
        int row = ci >> 5, cc = ci & 31; \
        cp16(dst + row * (LDH*4) + cc * 16, \
             At + (size_t)((J) * 32 + row) * MT + bm + cc * 4); \
        cp16(dst + STG_BY + row * (LDH*4) + cc * 16, \
             Wt + (size_t)((J) * 32 + row) * DM + bn + cc * 4); \
    } \
    asm volatile("cp.async.commit_group;" ::: "memory"); \
} while (0)

    LOAD_STAGE(0, 0);
    LOAD_STAGE(1, 1);

    for (int j = 0; j < 16; j++) {
        if (j < 15) asm volatile("cp.async.wait_group 1;" ::: "memory");
        else        asm volatile("cp.async.wait_group 0;" ::: "memory");
        __syncthreads();

        const __half2* Ab = smh + (j % 3) * 2 * STG_H2;
        const __half2* Wb = Ab + STG_H2;
#pragma unroll
        for (int ks = 0; ks < 4; ks++) {
            const int kp0 = ks * 8 + tig;
            uint4 ua0 = *(const uint4*)&Ab[kp0*LDH     + wmh      + g*4];
            uint4 ua1 = *(const uint4*)&Ab[kp0*LDH     + wmh + 32 + g*4];
            uint4 ua2 = *(const uint4*)&Ab[(kp0+4)*LDH + wmh      + g*4];
            uint4 ua3 = *(const uint4*)&Ab[(kp0+4)*LDH + wmh + 32 + g*4];
            uint4 ub00 = *(const uint4*)&Wb[kp0*LDH     + wnc      + g*4];
            uint4 ub01 = *(const uint4*)&Wb[kp0*LDH     + wnc + 32 + g*4];
            uint4 ub10 = *(const uint4*)&Wb[(kp0+4)*LDH + wnc      + g*4];
            uint4 ub11 = *(const uint4*)&Wb[(kp0+4)*LDH + wnc + 32 + g*4];
            const uint32_t a0[4] = {ua0.x, ua0.y, ua0.z, ua0.w};
            const uint32_t a1[4] = {ua1.x, ua1.y, ua1.z, ua1.w};
            const uint32_t a2[4] = {ua2.x, ua2.y, ua2.z, ua2.w};
            const uint32_t a3[4] = {ua3.x, ua3.y, ua3.z, ua3.w};
            const uint32_t b0[8] = {ub00.x,ub00.y,ub00.z,ub00.w, ub01.x,ub01.y,ub01.z,ub01.w};
            const uint32_t b1[8] = {ub10.x,ub10.y,ub10.z,ub10.w, ub11.x,ub11.y,ub11.z,ub11.w};
#pragma unroll
            for (int mt = 0; mt < 4; mt++)
#pragma unroll
                for (int nt = 0; nt < 8; nt++)
                    mma16(acc[mt][nt], a0[mt], a1[mt], a2[mt], a3[mt],
                          b0[nt], b1[nt]);
        }
        if (j + 2 < 16) LOAD_STAGE(j + 2, (j + 2) % 3);
    }
#undef LOAD_STAGE

#pragma unroll
    for (int mt = 0; mt < 4; mt++) {
        int r0 = bm + (wid >> 1) * 64 + mt * 16 + g;
#pragma unroll
        for (int nt = 0; nt < 8; nt++) {
            int c = bn + (wid & 1) * 64 + (nt >> 2) * 32 + (nt & 3) * 8 + 2 * tig;
            float2 bv = *(const float2*)(bias + c);
            *(uint32_t*)&Ch[(size_t)r0 * DM + c] =
                packh2(acc[mt][nt][0] + bv.x, acc[mt][nt][1] + bv.y);
            *(uint32_t*)&Ch[(size_t)(r0 + 8) * DM + c] =
                packh2(acc[mt][nt][2] + bv.x, acc[mt][nt][3] + bv.y);
        }
    }
}

// ---------------- Flash attention v8 (unchanged from R14) -----------------------
#define LDK2 88
#define ABUF (2*32*LDK2)      // half2 per stage buffer (Ks+Vs)
#define ASMEM (2*ABUF*4)      // 45056

__device__ __forceinline__ void attn_ldg(
    const __half* __restrict__ Kh, const __half* __restrict__ V,
    size_t base, int k0, int kkey, int kd0, int vkp, int vdg,
    uint32_t* kw, uint32_t* av, uint32_t* bv)
{
    const __half* kptr = Kh + base + (size_t)(k0 + kkey) * DM + kd0;
    uint4 u0 = *(const uint4*)kptr;
    uint4 u1 = *(const uint4*)(kptr + 8);
    uint4 u2 = *(const uint4*)(kptr + 16);
    uint4 u3 = *(const uint4*)(kptr + 24);
    kw[0]=u0.x; kw[1]=u0.y; kw[2]=u0.z; kw[3]=u0.w;
    kw[4]=u1.x; kw[5]=u1.y; kw[6]=u1.z; kw[7]=u1.w;
    kw[8]=u2.x; kw[9]=u2.y; kw[10]=u2.z; kw[11]=u2.w;
    kw[12]=u3.x; kw[13]=u3.y; kw[14]=u3.z; kw[15]=u3.w;
    const __half* v0 = V + base + (size_t)(k0 + 2*vkp) * DM + vdg;
    uint4 a  = *(const uint4*)v0;
    uint4 a2 = *(const uint4*)(v0 + 8);
    uint4 b  = *(const uint4*)(v0 + DM);
    uint4 b2 = *(const uint4*)(v0 + DM + 8);
    av[0]=a.x; av[1]=a.y; av[2]=a.z; av[3]=a.w;
    av[4]=a2.x; av[5]=a2.y; av[6]=a2.z; av[7]=a2.w;
    bv[0]=b.x; bv[1]=b.y; bv[2]=b.z; bv[3]=b.w;
    bv[4]=b2.x; bv[5]=b2.y; bv[6]=b2.z; bv[7]=b2.w;
}

__device__ __forceinline__ void attn_sts(
    __half2* Ks, __half2* Vs, int kc, int dp, int vkp, int vdg,
    const uint32_t* kw, const uint32_t* av, const uint32_t* bv)
{
#pragma unroll
    for (int i = 0; i < 16; i++)
        *(uint32_t*)&Ks[(dp + i)*LDK2 + kc] = kw[i];
    __half2* vrow = &Vs[vkp*LDK2];
#pragma unroll
    for (int e = 0; e < 8; e++) {
        int d0 = vdg + 2*e, d1 = d0 + 1;
        int c0 = (d0 & 7) * 8 + (d0 >> 3);
        int c1 = (d1 & 7) * 8 + (d1 >> 3);
        *(uint32_t*)&vrow[c0] = prmt(av[e], bv[e], 0x5410);
        *(uint32_t*)&vrow[c1] = prmt(av[e], bv[e], 0x7632);
    }
}

__global__ __launch_bounds__(128, 2) void attn_h(
    const __half* __restrict__ Q, const __half* __restrict__ Kh,
    const __half* __restrict__ V, const __half* __restrict__ Vpost,
    __half* __restrict__ Oh, __half2* __restrict__ Oat)
{
    extern __shared__ __half2 smh[];

    const int tid = threadIdx.x, wid = tid >> 5, lane = tid & 31;
    const int g = lane >> 2, tig = lane & 3;
    const int wq = wid << 5;           // 32 q rows per warp
    const int q0 = blockIdx.x << 7;
    const int bh = blockIdx.y, b = bh >> 4, h = bh & 15;
    const size_t base = (size_t)b * SS * DM + (size_t)h * DH;
    const float C = 0.125f * 1.44269504f;

    const int kkey = tid & 63, kd0 = (tid >> 6) << 5;
    const int kc = ((kkey & 7) << 3) | (kkey >> 3);
    const int dp = kd0 >> 1;
    const int vkp = tid >> 2, vdg = (tid & 3) << 4;

    uint32_t qa[2][4][4];
#pragma unroll
    for (int ms = 0; ms < 2; ms++) {
        const __half* qb = Q + base + (size_t)(q0 + wq + ms*16 + g) * DM;
#pragma unroll
        for (int ks = 0; ks < 4; ks++) {
            const int d0 = 2 * (ks * 8 + tig);
            qa[ms][ks][0] = *(const uint32_t*)(qb + d0);
            qa[ms][ks][1] = *(const uint32_t*)(qb + 8*DM + d0);
            qa[ms][ks][2] = *(const uint32_t*)(qb + d0 + 8);
            qa[ms][ks][3] = *(const uint32_t*)(qb + 8*DM + d0 + 8);
        }
    }

    float o[2][8][4];
#pragma unroll
    for (int ms = 0; ms < 2; ms++)
#pragma unroll
        for (int nt = 0; nt < 8; nt++)
#pragma unroll
            for (int e = 0; e < 4; e++) o[ms][nt][e] = 0.f;
    float mm[2][2], ll[2][2];
#pragma unroll
    for (int ms = 0; ms < 2; ms++) { mm[ms][0] = mm[ms][1] = -1e30f; ll[ms][0] = ll[ms][1] = 0.f; }

    uint32_t kw[16], av[8], bv[8];
    attn_ldg(Kh, V, base, 0, kkey, kd0, vkp, vdg, kw, av, bv);
    attn_sts(smh, smh + 32*LDK2, kc, dp, vkp, vdg, kw, av, bv);
    __syncthreads();

    for (int kt = 0; kt < 16; kt++) {
        const int cur = kt & 1;
        const __half2* Ks = smh + cur * ABUF;
        const __half2* Vs = Ks + 32*LDK2;

        if (kt < 15)
            attn_ldg(Kh, V, base, (kt + 1) << 6, kkey, kd0, vkp, vdg, kw, av, bv);

        float s[2][8][4];
#pragma unroll
        for (int ms = 0; ms < 2; ms++)
#pragma unroll
            for (int nt = 0; nt < 8; nt++)
#pragma unroll
                for (int e = 0; e < 4; e++) s[ms][nt][e] = 0.f;
#pragma unroll
        for (int ks = 0; ks < 4; ks++) {
            const int dp0 = ks * 8 + tig;
            uint4 u0 = *(const uint4*)&Ks[dp0*LDK2 + g*8];
            uint4 u1 = *(const uint4*)&Ks[dp0*LDK2 + g*8 + 4];
            uint4 u2 = *(const uint4*)&Ks[(dp0+4)*LDK2 + g*8];
            uint4 u3 = *(const uint4*)&Ks[(dp0+4)*LDK2 + g*8 + 4];
            const uint32_t b0[8] = {u0.x,u0.y,u0.z,u0.w, u1.x,u1.y,u1.z,u1.w};
            const uint32_t b1[8] = {u2.x,u2.y,u2.z,u2.w, u3.x,u3.y,u3.z,u3.w};
#pragma unroll
            for (int ms = 0; ms < 2; ms++)
#pragma unroll
                for (int nt = 0; nt < 8; nt++)
                    mma16(s[ms][nt], qa[ms][ks][0], qa[ms][ks][1],
                          qa[ms][ks][2], qa[ms][ks][3], b0[nt], b1[nt]);
        }

        uint32_t p[2][4][4];
        float al[2][2];
#pragma unroll
        for (int ms = 0; ms < 2; ms++) {
            float tm0 = -1e30f, tm1 = -1e30f;
#pragma unroll
            for (int nt = 0; nt < 8; nt++) {
                tm0 = fmaxf(tm0, fmaxf(s[ms][nt][0], s[ms][nt][1]));
                tm1 = fmaxf(tm1, fmaxf(s[ms][nt][2], s[ms][nt][3]));
            }
            tm0 = fmaxf(tm0, __shfl_xor_sync(0xffffffffu, tm0, 1));
            tm0 = fmaxf(tm0, __shfl_xor_sync(0xffffffffu, tm0, 2));
            tm1 = fmaxf(tm1, __shfl_xor_sync(0xffffffffu, tm1, 1));
            tm1 = fmaxf(tm1, __shfl_xor_sync(0xffffffffu, tm1, 2));
            float mn0 = fmaxf(mm[ms][0], tm0), mn1 = fmaxf(mm[ms][1], tm1);
            al[ms][0] = exp2f((mm[ms][0] - mn0) * C);
            al[ms][1] = exp2f((mm[ms][1] - mn1) * C);
            float rs0 = 0.f, rs1 = 0.f;
#pragma unroll
            for (int ks = 0; ks < 4; ks++) {
                float e00 = exp2f((s[ms][2*ks][0]   - mn0) * C), e01 = exp2f((s[ms][2*ks][1]   - mn0) * C);
                float e02 = exp2f((s[ms][2*ks][2]   - mn1) * C), e03 = exp2f((s[ms][2*ks][3]   - mn1) * C);
                float e10 = exp2f((s[ms][2*ks+1][0] - mn0) * C), e11 = exp2f((s[ms][2*ks+1][1] - mn0) * C);
                float e12 = exp2f((s[ms][2*ks+1][2] - mn1) * C), e13 = exp2f((s[ms][2*ks+1][3] - mn1) * C);
                rs0 += (e00 + e01) + (e10 + e11);
                rs1 += (e02 + e03) + (e12 + e13);
                p[ms][ks][0] = packh2(e00, e01);
                p[ms][ks][1] = packh2(e02, e03);
                p[ms][ks][2] = packh2(e10, e11);
                p[ms][ks][3] = packh2(e12, e13);
            }
            rs0 += __shfl_xor_sync(0xffffffffu, rs0, 1);
            rs0 += __shfl_xor_sync(0xffffffffu, rs0, 2);
            rs1 += __shfl_xor_sync(0xffffffffu, rs1, 1);
            rs1 += __shfl_xor_sync(0xffffffffu, rs1, 2);
            ll[ms][0] = ll[ms][0] * al[ms][0] + rs0;  mm[ms][0] = mn0;
            ll[ms][1] = ll[ms][1] * al[ms][1] + rs1;  mm[ms][1] = mn1;
        }

#pragma unroll
        for (int ms = 0; ms < 2; ms++)
#pragma unroll
            for (int nt = 0; nt < 8; nt++) {
                o[ms][nt][0] *= al[ms][0]; o[ms][nt][1] *= al[ms][0];
                o[ms][nt][2] *= al[ms][1]; o[ms][nt][3] *= al[ms][1];
            }
#pragma unroll
        for (int ks = 0; ks < 4; ks++) {
            const int kp0 = ks * 8 + tig;
            uint4 u0 = *(const uint4*)&Vs[kp0*LDK2 + g*8];
            uint4 u1 = *(const uint4*)&Vs[kp0*LDK2 + g*8 + 4];
            uint4 u2 = *(const uint4*)&Vs[(kp0+4)*LDK2 + g*8];
            uint4 u3 = *(const uint4*)&Vs[(kp0+4)*LDK2 + g*8 + 4];
            const uint32_t b0[8] = {u0.x,u0.y,u0.z,u0.w, u1.x,u1.y,u1.z,u1.w};
            const uint32_t b1[8] = {u2.x,u2.y,u2.z,u2.w, u3.x,u3.y,u3.z,u3.w};
#pragma unroll
            for (int ms = 0; ms < 2; ms++)
#pragma unroll
                for (int nt = 0; nt < 8; nt++)
                    mma16(o[ms][nt], p[ms][ks][0], p[ms][ks][1],
                          p[ms][ks][2], p[ms][ks][3], b0[nt], b1[nt]);
        }

        if (kt < 15) {
            __half2* KsN = smh + (cur ^ 1) * ABUF;
            attn_sts(KsN, KsN + 32*LDK2, kc, dp, vkp, vdg, kw, av, bv);
        }
        __syncthreads();
    }

#pragma unroll
    for (int ms = 0; ms < 2; ms++) {
        float il0 = 1.f / ll[ms][0], il1 = 1.f / ll[ms][1];
        const int r = q0 + wq + ms*16 + g;
        if (Oh) {
#pragma unroll
            for (int nt = 0; nt < 8; nt++) {
                int d0 = nt * 8 + 2 * tig;
                float o00 = o[ms][nt][0]*il0, o01 = o[ms][nt][1]*il0;
                float o10 = o[ms][nt][2]*il1, o11 = o[ms][nt][3]*il1;
                if (Vpost) {
                    uint32_t v0 = *(const uint32_t*)(Vpost + base + (size_t)r * DM + d0);
                    uint32_t v1 = *(const uint32_t*)(Vpost + base + (size_t)(r+8) * DM + d0);
                    float2 f0 = __half22float2(*(__half2*)&v0);
                    float2 f1 = __half22float2(*(__half2*)&v1);
                    o00 += f0.x; o01 += f0.y; o10 += f1.x; o11 += f1.y;
                }
                *(uint32_t*)&Oh[base + (size_t)r * DM + d0]     = packh2(o00, o01);
                *(uint32_t*)&Oh[base + (size_t)(r+8) * DM + d0] = packh2(o10, o11);
            }
        } else {
            const size_t mbase = (size_t)b * SS + q0;
            const int lq = wq + ms*16 + g;
            const int mp0 = ((lq >> 6) & 1) * 64 + ((lq >> 3) & 1) * 32 + (lq & 7) * 4 + ((lq >> 4) & 3);
            const int lq1 = lq + 8;
            const int mp1 = ((lq1 >> 6) & 1) * 64 + ((lq1 >> 3) & 1) * 32 + (lq1 & 7) * 4 + ((lq1 >> 4) & 3);
#pragma unroll
            for (int nt = 0; nt < 8; nt++) {
                const int kp = h * 32 + nt * 4 + tig;
                *(uint32_t*)&Oat[(size_t)kp * MT + mbase + mp0] =
                    packh2(o[ms][nt][0]*il0, o[ms][nt][1]*il0);
                *(uint32_t*)&Oat[(size_t)kp * MT + mbase + mp1] =
                    packh2(o[ms][nt][2]*il1, o[ms][nt][3]*il1);
            }
        }
    }
}

// ---------------- launch --------------------------------------------------------
extern "C" void kernel_launch(void* const* d_in, const int* in_sizes, int n_in,
                              void* d_out, int out_size) {
    (void)in_sizes; (void)n_in; (void)out_size;
    const float* gfeat = (const float*)d_in[0];
    const float* lfeat = (const float*)d_in[1];
    const float* tfeat = (const float*)d_in[2];
    const float* gqw = (const float*)d_in[3];  const float* gqb = (const float*)d_in[4];
    const float* gkw = (const float*)d_in[5];  const float* gkb = (const float*)d_in[6];
    const float* gvw = (const float*)d_in[7];  const float* gvb = (const float*)d_in[8];
    const float* pqw = (const float*)d_in[9];  const float* pqb = (const float*)d_in[10];
    const float* pkw = (const float*)d_in[11]; const float* pkb = (const float*)d_in[12];
    const float* pvw = (const float*)d_in[13]; const float* pvb = (const float*)d_in[14];
    const float* dw  = (const float*)d_in[15]; const float* db  = (const float*)d_in[16];
    float* out = (float*)d_out;

    __half2 *acts, *wts, *ctxat;
    __half *proj, *a2h;
    cudaGetSymbolAddress((void**)&acts,  g_acts);
    cudaGetSymbolAddress((void**)&wts,   g_wts);
    cudaGetSymbolAddress((void**)&proj,  g_proj);
    cudaGetSymbolAddress((void**)&a2h,   g_a2h);
    cudaGetSymbolAddress((void**)&ctxat, g_ctxat);

    __half* qh  = proj;
    __half* kh  = proj + 1*(size_t)MT*DM;
    __half* vh  = proj + 2*(size_t)MT*DM;
    __half* pqh = proj + 3*(size_t)MT*DM;
    __half* pkh = proj + 4*(size_t)MT*DM;
    __half* pvh = proj + 5*(size_t)MT*DM;

    cudaFuncSetAttribute(gemm_fp16,  cudaFuncAttributeMaxDynamicSharedMemorySize, GSMEM);
    cudaFuncSetAttribute(gemm_multi, cudaFuncAttributeMaxDynamicSharedMemorySize, GSMEM);
    cudaFuncSetAttribute(attn_h,     cudaFuncAttributeMaxDynamicSharedMemorySize, ASMEM);

    dim3 gg(DM/128, MT/128);          // (8, 32)
    dim3 gg3(3*DM/128, MT/128);       // 3-slot merged (24, 32)
    dim3 gg2(2*DM/128, MT/128);       // 2-slot merged (16, 32)
    dim3 ga(SS/128, BB*NH);           // (8, 64)
    dim3 gcw(DM/128, DM/32, 7);
    dim3 gca(MT/128, DM/32, 3);

    Ptrs7 wp = {{ gqw, gkw, gvw, pqw, pkw, pvw, dw }};
    Ptrs3 ap = {{ gfeat, lfeat, tfeat }};
    conv_w_all<<<gcw, 256>>>(wp, wts);
    conv_a_all<<<gca, 256>>>(ap, acts);

    const __half2* atG = acts;
    const __half2* atL = acts + ATS;
    const __half2* atT = acts + 2*ATS;

    // gq (A = gfeat), single slot
    gemm_fp16<<<gg, 128, GSMEM>>>(atG, wts, gqb, nullptr, qh);
    // {gk, gv, pq} share A = lfeat -> one wave-packed launch (slots 1..3)
    Bias3 bL = {{ gkb, gvb, pqb }};
    gemm_multi<<<gg3, 128, GSMEM>>>(atL, wts + 1*(size_t)WTS, bL, kh);
    // {pk, pv} share A = tfeat -> one launch (slots 4..5)
    Bias3 bT = {{ pkb, pvb, nullptr }};
    gemm_multi<<<gg2, 128, GSMEM>>>(atT, wts + 4*(size_t)WTS, bT, pkh);

    // att2+gv = softmax(pq pk^T/8) @ pv + gv
    attn_h<<<ga, 128, ASMEM>>>(pqh, pkh, pvh, vh, a2h, nullptr);
    // ctx = softmax(gq gk^T/8) @ (att2+gv) -> permuted at-layout
    attn_h<<<ga, 128, ASMEM>>>(qh, kh, a2h, nullptr, nullptr, ctxat);

    // dense: fp32 out
    gemm_fp16<<<gg, 128, GSMEM>>>(ctxat, wts + 6*(size_t)WTS, db, out, nullptr);
}

// round 16
// speedup vs baseline: 1.0004x; 1.0004x over previous
#include <cuda_runtime.h>
#include <cuda_fp16.h>
#include <cstdint>

#define DM 1024     // d_model
#define NH 16       // heads
#define DH 64       // head dim
#define BB 4        // batch
#define SS 1024     // seq
#define MT (BB*SS)  // 4096 rows

#define ATS ((DM/2)*MT)   // half2 per activation slot
#define WTS ((DM/2)*DM)   // half2 per weight slot

// ---------------- scratch ----------------
__device__ __half2 g_acts[3*ATS];    // conv'd activations: gfeat, lfeat, tfeat
__device__ __half2 g_wts[7*WTS];     // conv'd weights: gq,gk,gv,pq,pk,pv,dense
__device__ __half  g_proj[6*(size_t)MT*DM];  // qh,kh,vh,pqh,pkh,pvh
__device__ __half  g_a2h[(size_t)MT*DM];     // att2 + gv
__device__ __half2 g_ctxat[ATS];     // ctx in permuted at-layout (attn#2 output)

struct Ptrs7 { const float* p[7]; };
struct Ptrs3 { const float* p[3]; };

__device__ __forceinline__ void mma16(float* c,
    uint32_t a0, uint32_t a1, uint32_t a2, uint32_t a3, uint32_t b0, uint32_t b1) {
    asm volatile(
        "mma.sync.aligned.m16n8k16.row.col.f32.f16.f16.f32 "
        "{%0,%1,%2,%3},{%4,%5,%6,%7},{%8,%9},{%0,%1,%2,%3};\n"
        : "+f"(c[0]), "+f"(c[1]), "+f"(c[2]), "+f"(c[3])
        : "r"(a0), "r"(a1), "r"(a2), "r"(a3), "r"(b0), "r"(b1));
}
__device__ __forceinline__ uint32_t smem_u32(const void* p) {
    uint32_t a;
    asm("{ .reg .u64 t; cvta.to.shared.u64 t, %1; cvt.u32.u64 %0, t; }" : "=r"(a) : "l"(p));
    return a;
}
__device__ __forceinline__ void cp16(uint32_t dst, const void* src) {
    asm volatile("cp.async.cg.shared.global [%0], [%1], 16;" :: "r"(dst), "l"(src) : "memory");
}
__device__ __forceinline__ uint32_t packh2(float lo, float hi) {
    uint32_t r;
    asm("cvt.rn.f16x2.f32 %0, %1, %2;" : "=r"(r) : "f"(hi), "f"(lo));
    return r;
}
__device__ __forceinline__ uint32_t prmt(uint32_t a, uint32_t b, uint32_t s) {
    uint32_t d;
    asm("prmt.b32 %0, %1, %2, %3;" : "=r"(d) : "r"(a), "r"(b), "r"(s));
    return d;
}

// ---------------- single merged convert kernel ----------------------------------
// blocks [0,1792): weights (7 slots x 8 m-tiles x 32 k-tiles)
// blocks [1792,4864): activations (3 slots x 32 m-tiles x 32 k-tiles)
__device__ __forceinline__ void conv_body(
    const float* __restrict__ in, __half2* __restrict__ out, int Rm, int isW,
    int m0, int k0)
{
    __shared__ float ts[128][33];
#pragma unroll
    for (int i = 0; i < 4; i++) {
        int idx = threadIdx.x + (i << 8);
        int ml = idx >> 3, kc = (idx & 7) << 2;
        float4 v = *(const float4*)(in + (size_t)(m0 + ml) * 1024 + k0 + kc);
        ts[ml][kc] = v.x; ts[ml][kc+1] = v.y; ts[ml][kc+2] = v.z; ts[ml][kc+3] = v.w;
    }
    __syncthreads();
#pragma unroll
    for (int i = 0; i < 8; i++) {
        int idx = threadIdx.x + (i << 8);      // 0..2047
        int kp = idx >> 7, sc = idx & 127;
        int ml;
        if (isW) {
            int ch = sc >> 5, r = sc & 31, gg = (r >> 2) & 7, nt = r & 3;
            ml = ch * 32 + nt * 8 + gg;
        } else {
            int hf = sc >> 6, r = sc & 63, hi = (r >> 5) & 1, gg = (r >> 2) & 7, mt = r & 3;
            ml = hf * 64 + mt * 16 + hi * 8 + gg;
        }
        out[(size_t)((k0 >> 1) + kp) * Rm + m0 + sc] =
            __floats2half2_rn(ts[ml][2*kp], ts[ml][2*kp+1]);
    }
}
__global__ __launch_bounds__(256) void conv_all(
    Ptrs7 wsrc, Ptrs3 asrc, __half2* __restrict__ wts, __half2* __restrict__ acts)
{
    int idx = blockIdx.x;
    if (idx < 1792) {                 // weights: 7 * 256
        int z = idx >> 8, rem = idx & 255;
        conv_body(wsrc.p[z], wts + (size_t)z * WTS, DM, 1,
                  (rem & 7) << 7, (rem >> 3) << 5);
    } else {                          // activations: 3 * 1024
        idx -= 1792;
        int z = idx >> 10, rem = idx & 1023;
        conv_body(asrc.p[z], acts + (size_t)z * ATS, MT, 0,
                  (rem & 31) << 7, (rem >> 5) << 5);
    }
}

// ---------------- GEMM fp16 (proven R9/R14 shape, unchanged) -------------------
#define LDH 136
#define STG_H2 (32*LDH)
#define STG_BY (STG_H2*4)     // 17408 bytes
#define GSMEM (3*2*STG_BY)    // 104448

__global__ __launch_bounds__(128, 2) void gemm_fp16(
    const __half2* __restrict__ At, const __half2* __restrict__ Wt,
    const float* __restrict__ bias, float* __restrict__ Cf, __half* __restrict__ Ch)
{
    extern __shared__ __half2 smh[];
    const uint32_t sb = smem_u32(smh);
    const int tid = threadIdx.x, wid = tid >> 5, lane = tid & 31;
    const int g = lane >> 2, tig = lane & 3;
    const int wmh = (wid >> 1) * 64;
    const int wnc = (wid & 1) * 64;
    const int bm = blockIdx.y << 7, bn = blockIdx.x << 7;

    float acc[4][8][4];
#pragma unroll
    for (int i = 0; i < 4; i++)
#pragma unroll
        for (int j = 0; j < 8; j++)
#pragma unroll
            for (int e = 0; e < 4; e++) acc[i][j][e] = 0.f;

#define LOAD_STAGE(J, S) do { \
    uint32_t dst = sb + (uint32_t)(S) * 2 * STG_BY; \
    _Pragma("unroll") \
    for (int p = 0; p < 8; p++) { \
        int ci = tid + (p << 7); \
        int row = ci >> 5, cc = ci & 31; \
        cp16(dst + row * (LDH*4) + cc * 16, \
             At + (size_t)((J) * 32 + row) * MT + bm + cc * 4); \
        cp16(dst + STG_BY + row * (LDH*4) + cc * 16, \
             Wt + (size_t)((J) * 32 + row) * DM + bn + cc * 4); \
    } \
    asm volatile("cp.async.commit_group;" ::: "memory"); \
} while (0)

    LOAD_STAGE(0, 0);
    LOAD_STAGE(1, 1);

    for (int j = 0; j < 16; j++) {
        if (j < 15) asm volatile("cp.async.wait_group 1;" ::: "memory");
        else        asm volatile("cp.async.wait_group 0;" ::: "memory");
        __syncthreads();

        const __half2* Ab = smh + (j % 3) * 2 * STG_H2;
        const __half2* Wb = Ab + STG_H2;
#pragma unroll
        for (int ks = 0; ks < 4; ks++) {
            const int kp0 = ks * 8 + tig;
            uint4 ua0 = *(const uint4*)&Ab[kp0*LDH     + wmh      + g*4];
            uint4 ua1 = *(const uint4*)&Ab[kp0*LDH     + wmh + 32 + g*4];
            uint4 ua2 = *(const uint4*)&Ab[(kp0+4)*LDH + wmh      + g*4];
            uint4 ua3 = *(const uint4*)&Ab[(kp0+4)*LDH + wmh + 32 + g*4];
            uint4 ub00 = *(const uint4*)&Wb[kp0*LDH     + wnc      + g*4];
            uint4 ub01 = *(const uint4*)&Wb[kp0*LDH     + wnc + 32 + g*4];
            uint4 ub10 = *(const uint4*)&Wb[(kp0+4)*LDH + wnc      + g*4];
            uint4 ub11 = *(const uint4*)&Wb[(kp0+4)*LDH + wnc + 32 + g*4];
            const uint32_t a0[4] = {ua0.x, ua0.y, ua0.z, ua0.w};
            const uint32_t a1[4] = {ua1.x, ua1.y, ua1.z, ua1.w};
            const uint32_t a2[4] = {ua2.x, ua2.y, ua2.z, ua2.w};
            const uint32_t a3[4] = {ua3.x, ua3.y, ua3.z, ua3.w};
            const uint32_t b0[8] = {ub00.x,ub00.y,ub00.z,ub00.w, ub01.x,ub01.y,ub01.z,ub01.w};
            const uint32_t b1[8] = {ub10.x,ub10.y,ub10.z,ub10.w, ub11.x,ub11.y,ub11.z,ub11.w};
#pragma unroll
            for (int mt = 0; mt < 4; mt++)
#pragma unroll
                for (int nt = 0; nt < 8; nt++)
                    mma16(acc[mt][nt], a0[mt], a1[mt], a2[mt], a3[mt],
                          b0[nt], b1[nt]);
        }
        if (j + 2 < 16) LOAD_STAGE(j + 2, (j + 2) % 3);
    }
#undef LOAD_STAGE

#pragma unroll
    for (int mt = 0; mt < 4; mt++) {
        int r0 = bm + (wid >> 1) * 64 + mt * 16 + g;
#pragma unroll
        for (int nt = 0; nt < 8; nt++) {
            int c = bn + (wid & 1) * 64 + (nt >> 2) * 32 + (nt & 3) * 8 + 2 * tig;
            float2 bv = *(const float2*)(bias + c);
            float o00 = acc[mt][nt][0] + bv.x, o01 = acc[mt][nt][1] + bv.y;
            float o10 = acc[mt][nt][2] + bv.x, o11 = acc[mt][nt][3] + bv.y;
            if (Ch) {
                *(uint32_t*)&Ch[(size_t)r0 * DM + c]       = packh2(o00, o01);
                *(uint32_t*)&Ch[(size_t)(r0 + 8) * DM + c] = packh2(o10, o11);
            } else {
                *(float2*)(Cf + (size_t)r0 * DM + c)       = make_float2(o00, o01);
                *(float2*)(Cf + (size_t)(r0 + 8) * DM + c) = make_float2(o10, o11);
            }
        }
    }
}

// ---------------- Flash attention v8 (R14, + FFMA-folded exp2) ------------------
#define LDK2 88
#define ABUF (2*32*LDK2)      // half2 per stage buffer (Ks+Vs)
#define ASMEM (2*ABUF*4)      // 45056

__device__ __forceinline__ void attn_ldg(
    const __half* __restrict__ Kh, const __half* __restrict__ V,
    size_t base, int k0, int kkey, int kd0, int vkp, int vdg,
    uint32_t* kw, uint32_t* av, uint32_t* bv)
{
    const __half* kptr = Kh + base + (size_t)(k0 + kkey) * DM + kd0;
    uint4 u0 = *(const uint4*)kptr;
    uint4 u1 = *(const uint4*)(kptr + 8);
    uint4 u2 = *(const uint4*)(kptr + 16);
    uint4 u3 = *(const uint4*)(kptr + 24);
    kw[0]=u0.x; kw[1]=u0.y; kw[2]=u0.z; kw[3]=u0.w;
    kw[4]=u1.x; kw[5]=u1.y; kw[6]=u1.z; kw[7]=u1.w;
    kw[8]=u2.x; kw[9]=u2.y; kw[10]=u2.z; kw[11]=u2.w;
    kw[12]=u3.x; kw[13]=u3.y; kw[14]=u3.z; kw[15]=u3.w;
    const __half* v0 = V + base + (size_t)(k0 + 2*vkp) * DM + vdg;
    uint4 a  = *(const uint4*)v0;
    uint4 a2 = *(const uint4*)(v0 + 8);
    uint4 b  = *(const uint4*)(v0 + DM);
    uint4 b2 = *(const uint4*)(v0 + DM + 8);
    av[0]=a.x; av[1]=a.y; av[2]=a.z; av[3]=a.w;
    av[4]=a2.x; av[5]=a2.y; av[6]=a2.z; av[7]=a2.w;
    bv[0]=b.x; bv[1]=b.y; bv[2]=b.z; bv[3]=b.w;
    bv[4]=b2.x; bv[5]=b2.y; bv[6]=b2.z; bv[7]=b2.w;
}

__device__ __forceinline__ void attn_sts(
    __half2* Ks, __half2* Vs, int kc, int dp, int vkp, int vdg,
    const uint32_t* kw, const uint32_t* av, const uint32_t* bv)
{
#pragma unroll
    for (int i = 0; i < 16; i++)
        *(uint32_t*)&Ks[(dp + i)*LDK2 + kc] = kw[i];
    __half2* vrow = &Vs[vkp*LDK2];
#pragma unroll
    for (int e = 0; e < 8; e++) {
        int d0 = vdg + 2*e, d1 = d0 + 1;
        int c0 = (d0 & 7) * 8 + (d0 >> 3);
        int c1 = (d1 & 7) * 8 + (d1 >> 3);
        *(uint32_t*)&vrow[c0] = prmt(av[e], bv[e], 0x5410);
        *(uint32_t*)&vrow[c1] = prmt(av[e], bv[e], 0x7632);
    }
}

__global__ __launch_bounds__(128, 2) void attn_h(
    const __half* __restrict__ Q, const __half* __restrict__ Kh,
    const __half* __restrict__ V, const __half* __restrict__ Vpost,
    __half* __restrict__ Oh, __half2* __restrict__ Oat)
{
    extern __shared__ __half2 smh[];

    const int tid = threadIdx.x, wid = tid >> 5, lane = tid & 31;
    const int g = lane >> 2, tig = lane & 3;
    const int wq = wid << 5;           // 32 q rows per warp
    const int q0 = blockIdx.x << 7;
    const int bh = blockIdx.y, b = bh >> 4, h = bh & 15;
    const size_t base = (size_t)b * SS * DM + (size_t)h * DH;
    const float C = 0.125f * 1.44269504f;

    const int kkey = tid & 63, kd0 = (tid >> 6) << 5;
    const int kc = ((kkey & 7) << 3) | (kkey >> 3);
    const int dp = kd0 >> 1;
    const int vkp = tid >> 2, vdg = (tid & 3) << 4;

    uint32_t qa[2][4][4];
#pragma unroll
    for (int ms = 0; ms < 2; ms++) {
        const __half* qb = Q + base + (size_t)(q0 + wq + ms*16 + g) * DM;
#pragma unroll
        for (int ks = 0; ks < 4; ks++) {
            const int d0 = 2 * (ks * 8 + tig);
            qa[ms][ks][0] = *(const uint32_t*)(qb + d0);
            qa[ms][ks][1] = *(const uint32_t*)(qb + 8*DM + d0);
            qa[ms][ks][2] = *(const uint32_t*)(qb + d0 + 8);
            qa[ms][ks][3] = *(const uint32_t*)(qb + 8*DM + d0 + 8);
        }
    }

    float o[2][8][4];
#pragma unroll
    for (int ms = 0; ms < 2; ms++)
#pragma unroll
        for (int nt = 0; nt < 8; nt++)
#pragma unroll
            for (int e = 0; e < 4; e++) o[ms][nt][e] = 0.f;
    float mm[2][2], ll[2][2];
#pragma unroll
    for (int ms = 0; ms < 2; ms++) { mm[ms][0] = mm[ms][1] = -1e30f; ll[ms][0] = ll[ms][1] = 0.f; }

    uint32_t kw[16], av[8], bv[8];
    attn_ldg(Kh, V, base, 0, kkey, kd0, vkp, vdg, kw, av, bv);
    attn_sts(smh, smh + 32*LDK2, kc, dp, vkp, vdg, kw, av, bv);
    __syncthreads();

    for (int kt = 0; kt < 16; kt++) {
        const int cur = kt & 1;
        const __half2* Ks = smh + cur * ABUF;
        const __half2* Vs = Ks + 32*LDK2;

        if (kt < 15)
            attn_ldg(Kh, V, base, (kt + 1) << 6, kkey, kd0, vkp, vdg, kw, av, bv);

        float s[2][8][4];
#pragma unroll
        for (int ms = 0; ms < 2; ms++)
#pragma unroll
            for (int nt = 0; nt < 8; nt++)
#pragma unroll
                for (int e = 0; e < 4; e++) s[ms][nt][e] = 0.f;
#pragma unroll
        for (int ks = 0; ks < 4; ks++) {
            const int dp0 = ks * 8 + tig;
            uint4 u0 = *(const uint4*)&Ks[dp0*LDK2 + g*8];
            uint4 u1 = *(const uint4*)&Ks[dp0*LDK2 + g*8 + 4];
            uint4 u2 = *(const uint4*)&Ks[(dp0+4)*LDK2 + g*8];
            uint4 u3 = *(const uint4*)&Ks[(dp0+4)*LDK2 + g*8 + 4];
            const uint32_t b0[8] = {u0.x,u0.y,u0.z,u0.w, u1.x,u1.y,u1.z,u1.w};
            const uint32_t b1[8] = {u2.x,u2.y,u2.z,u2.w, u3.x,u3.y,u3.z,u3.w};
#pragma unroll
            for (int ms = 0; ms < 2; ms++)
#pragma unroll
                for (int nt = 0; nt < 8; nt++)
                    mma16(s[ms][nt], qa[ms][ks][0], qa[ms][ks][1],
                          qa[ms][ks][2], qa[ms][ks][3], b0[nt], b1[nt]);
        }

        uint32_t p[2][4][4];
        float al[2][2];
#pragma unroll
        for (int ms = 0; ms < 2; ms++) {
            float tm0 = -1e30f, tm1 = -1e30f;
#pragma unroll
            for (int nt = 0; nt < 8; nt++) {
                tm0 = fmaxf(tm0, fmaxf(s[ms][nt][0], s[ms][nt][1]));
                tm1 = fmaxf(tm1, fmaxf(s[ms][nt][2], s[ms][nt][3]));
            }
            tm0 = fmaxf(tm0, __shfl_xor_sync(0xffffffffu, tm0, 1));
            tm0 = fmaxf(tm0, __shfl_xor_sync(0xffffffffu, tm0, 2));
            tm1 = fmaxf(tm1, __shfl_xor_sync(0xffffffffu, tm1, 1));
            tm1 = fmaxf(tm1, __shfl_xor_sync(0xffffffffu, tm1, 2));
            float mn0 = fmaxf(mm[ms][0], tm0), mn1 = fmaxf(mm[ms][1], tm1);
            const float mnC0 = mn0 * C, mnC1 = mn1 * C;    // hoisted: exp2(s*C - mnC)
            al[ms][0] = exp2f(fmaf(mm[ms][0], C, -mnC0));
            al[ms][1] = exp2f(fmaf(mm[ms][1], C, -mnC1));
            float rs0 = 0.f, rs1 = 0.f;
#pragma unroll
            for (int ks = 0; ks < 4; ks++) {
                float e00 = exp2f(fmaf(s[ms][2*ks][0],   C, -mnC0)), e01 = exp2f(fmaf(s[ms][2*ks][1],   C, -mnC0));
                float e02 = exp2f(fmaf(s[ms][2*ks][2],   C, -mnC1)), e03 = exp2f(fmaf(s[ms][2*ks][3],   C, -mnC1));
                float e10 = exp2f(fmaf(s[ms][2*ks+1][0], C, -mnC0)), e11 = exp2f(fmaf(s[ms][2*ks+1][1], C, -mnC0));
                float e12 = exp2f(fmaf(s[ms][2*ks+1][2], C, -mnC1)), e13 = exp2f(fmaf(s[ms][2*ks+1][3], C, -mnC1));
                rs0 += (e00 + e01) + (e10 + e11);
                rs1 += (e02 + e03) + (e12 + e13);
                p[ms][ks][0] = packh2(e00, e01);
                p[ms][ks][1] = packh2(e02, e03);
                p[ms][ks][2] = packh2(e10, e11);
                p[ms][ks][3] = packh2(e12, e13);
            }
            rs0 += __shfl_xor_sync(0xffffffffu, rs0, 1);
            rs0 += __shfl_xor_sync(0xffffffffu, rs0, 2);
            rs1 += __shfl_xor_sync(0xffffffffu, rs1, 1);
            rs1 += __shfl_xor_sync(0xffffffffu, rs1, 2);
            ll[ms][0] = ll[ms][0] * al[ms][0] + rs0;  mm[ms][0] = mn0;
            ll[ms][1] = ll[ms][1] * al[ms][1] + rs1;  mm[ms][1] = mn1;
        }

#pragma unroll
        for (int ms = 0; ms < 2; ms++)
#pragma unroll
            for (int nt = 0; nt < 8; nt++) {
                o[ms][nt][0] *= al[ms][0]; o[ms][nt][1] *= al[ms][0];
                o[ms][nt][2] *= al[ms][1]; o[ms][nt][3] *= al[ms][1];
            }
#pragma unroll
        for (int ks = 0; ks < 4; ks++) {
            const int kp0 = ks * 8 + tig;
            uint4 u0 = *(const uint4*)&Vs[kp0*LDK2 + g*8];
            uint4 u1 = *(const uint4*)&Vs[kp0*LDK2 + g*8 + 4];
            uint4 u2 = *(const uint4*)&Vs[(kp0+4)*LDK2 + g*8];
            uint4 u3 = *(const uint4*)&Vs[(kp0+4)*LDK2 + g*8 + 4];
            const uint32_t b0[8] = {u0.x,u0.y,u0.z,u0.w, u1.x,u1.y,u1.z,u1.w};
            const uint32_t b1[8] = {u2.x,u2.y,u2.z,u2.w, u3.x,u3.y,u3.z,u3.w};
#pragma unroll
            for (int ms = 0; ms < 2; ms++)
#pragma unroll
                for (int nt = 0; nt < 8; nt++)
                    mma16(o[ms][nt], p[ms][ks][0], p[ms][ks][1],
                          p[ms][ks][2], p[ms][ks][3], b0[nt], b1[nt]);
        }

        if (kt < 15) {
            __half2* KsN = smh + (cur ^ 1) * ABUF;
            attn_sts(KsN, KsN + 32*LDK2, kc, dp, vkp, vdg, kw, av, bv);
        }
        __syncthreads();
    }

#pragma unroll
    for (int ms = 0; ms < 2; ms++) {
        float il0 = 1.f / ll[ms][0], il1 = 1.f / ll[ms][1];
        const int r = q0 + wq + ms*16 + g;
        if (Oh) {
#pragma unroll
            for (int nt = 0; nt < 8; nt++) {
                int d0 = nt * 8 + 2 * tig;
                float o00 = o[ms][nt][0]*il0, o01 = o[ms][nt][1]*il0;
                float o10 = o[ms][nt][2]*il1, o11 = o[ms][nt][3]*il1;
                if (Vpost) {
                    uint32_t v0 = *(const uint32_t*)(Vpost + base + (size_t)r * DM + d0);
                    uint32_t v1 = *(const uint32_t*)(Vpost + base + (size_t)(r+8) * DM + d0);
                    float2 f0 = __half22float2(*(__half2*)&v0);
                    float2 f1 = __half22float2(*(__half2*)&v1);
                    o00 += f0.x; o01 += f0.y; o10 += f1.x; o11 += f1.y;
                }
                *(uint32_t*)&Oh[base + (size_t)r * DM + d0]     = packh2(o00, o01);
                *(uint32_t*)&Oh[base + (size_t)(r+8) * DM + d0] = packh2(o10, o11);
            }
        } else {
            const size_t mbase = (size_t)b * SS + q0;
            const int lq = wq + ms*16 + g;
            const int mp0 = ((lq >> 6) & 1) * 64 + ((lq >> 3) & 1) * 32 + (lq & 7) * 4 + ((lq >> 4) & 3);
            const int lq1 = lq + 8;
            const int mp1 = ((lq1 >> 6) & 1) * 64 + ((lq1 >> 3) & 1) * 32 + (lq1 & 7) * 4 + ((lq1 >> 4) & 3);
#pragma unroll
            for (int nt = 0; nt < 8; nt++) {
                const int kp = h * 32 + nt * 4 + tig;
                *(uint32_t*)&Oat[(size_t)kp * MT + mbase + mp0] =
                    packh2(o[ms][nt][0]*il0, o[ms][nt][1]*il0);
                *(uint32_t*)&Oat[(size_t)kp * MT + mbase + mp1] =
                    packh2(o[ms][nt][2]*il1, o[ms][nt][3]*il1);
            }
        }
    }
}

// ---------------- launch --------------------------------------------------------
extern "C" void kernel_launch(void* const* d_in, const int* in_sizes, int n_in,
                              void* d_out, int out_size) {
    (void)in_sizes; (void)n_in; (void)out_size;
    const float* gfeat = (const float*)d_in[0];
    const float* lfeat = (const float*)d_in[1];
    const float* tfeat = (const float*)d_in[2];
    const float* gqw = (const float*)d_in[3];  const float* gqb = (const float*)d_in[4];
    const float* gkw = (const float*)d_in[5];  const float* gkb = (const float*)d_in[6];
    const float* gvw = (const float*)d_in[7];  const float* gvb = (const float*)d_in[8];
    const float* pqw = (const float*)d_in[9];  const float* pqb = (const float*)d_in[10];
    const float* pkw = (const float*)d_in[11]; const float* pkb = (const float*)d_in[12];
    const float* pvw = (const float*)d_in[13]; const float* pvb = (const float*)d_in[14];
    const float* dw  = (const float*)d_in[15]; const float* db  = (const float*)d_in[16];
    float* out = (float*)d_out;

    __half2 *acts, *wts, *ctxat;
    __half *proj, *a2h;
    cudaGetSymbolAddress((void**)&acts,  g_acts);
    cudaGetSymbolAddress((void**)&wts,   g_wts);
    cudaGetSymbolAddress((void**)&proj,  g_proj);
    cudaGetSymbolAddress((void**)&a2h,   g_a2h);
    cudaGetSymbolAddress((void**)&ctxat, g_ctxat);

    __half* qh  = proj;
    __half* kh  = proj + 1*(size_t)MT*DM;
    __half* vh  = proj + 2*(size_t)MT*DM;
    __half* pqh = proj + 3*(size_t)MT*DM;
    __half* pkh = proj + 4*(size_t)MT*DM;
    __half* pvh = proj + 5*(size_t)MT*DM;

    cudaFuncSetAttribute(gemm_fp16, cudaFuncAttributeMaxDynamicSharedMemorySize, GSMEM);
    cudaFuncSetAttribute(attn_h,    cudaFuncAttributeMaxDynamicSharedMemorySize, ASMEM);

    dim3 gg(DM/128, MT/128);          // (8, 32)
    dim3 ga(SS/128, BB*NH);           // (8, 64)

    Ptrs7 wp = {{ gqw, gkw, gvw, pqw, pkw, pvw, dw }};
    Ptrs3 ap = {{ gfeat, lfeat, tfeat }};
    conv_all<<<4864, 256>>>(wp, ap, wts, acts);

    const __half2* atG = acts;
    const __half2* atL = acts + ATS;
    const __half2* atT = acts + 2*ATS;

#define GEMMH(A, wi, bias, dst) gemm_fp16<<<gg, 128, GSMEM>>>((A), wts + (wi)*(size_t)WTS, (bias), nullptr, (dst))
    GEMMH(atG, 0, gqb, qh);
    GEMMH(atL, 1, gkb, kh);
    GEMMH(atL, 2, gvb, vh);
    GEMMH(atL, 3, pqb, pqh);
    GEMMH(atT, 4, pkb, pkh);
    GEMMH(atT, 5, pvb, pvh);
#undef GEMMH

    // att2+gv = softmax(pq pk^T/8) @ pv + gv
    attn_h<<<ga, 128, ASMEM>>>(pqh, pkh, pvh, vh, a2h, nullptr);
    // ctx = softmax(gq gk^T/8) @ (att2+gv) -> permuted at-layout
    attn_h<<<ga, 128, ASMEM>>>(qh, kh, a2h, nullptr, nullptr, ctxat);

    // dense: fp32 out
    gemm_fp16<<<gg, 128, GSMEM>>>(ctxat, wts + 6*(size_t)WTS, db, out, nullptr);
}

// round 17
// speedup vs baseline: 1.0297x; 1.0293x over previous
#include <cuda_runtime.h>
#include <cuda_fp16.h>
#include <cstdint>

#define DM 1024     // d_model
#define NH 16       // heads
#define DH 64       // head dim
#define BB 4        // batch
#define SS 1024     // seq
#define MT (BB*SS)  // 4096 rows

#define ATS ((DM/2)*MT)   // half2 per activation slot
#define WTS ((DM/2)*DM)   // half2 per weight slot

// ---------------- scratch ----------------
__device__ __half2 g_acts[3*ATS];    // conv'd activations: gfeat, lfeat, tfeat
__device__ __half2 g_wts[7*WTS];     // conv'd weights: gq,gk,gv,pq,pk,pv,dense
__device__ __half  g_proj[6*(size_t)MT*DM];  // qh,kh,vh,pqh,pkh,pvh
__device__ __half  g_a2h[(size_t)MT*DM];     // att2 + gv
__device__ __half2 g_ctxat[ATS];     // ctx in permuted at-layout (attn#2 output)

struct Ptrs7 { const float* p[7]; };
struct Ptrs3 { const float* p[3]; };

__device__ __forceinline__ void mma16(float* c,
    uint32_t a0, uint32_t a1, uint32_t a2, uint32_t a3, uint32_t b0, uint32_t b1) {
    asm volatile(
        "mma.sync.aligned.m16n8k16.row.col.f32.f16.f16.f32 "
        "{%0,%1,%2,%3},{%4,%5,%6,%7},{%8,%9},{%0,%1,%2,%3};\n"
        : "+f"(c[0]), "+f"(c[1]), "+f"(c[2]), "+f"(c[3])
        : "r"(a0), "r"(a1), "r"(a2), "r"(a3), "r"(b0), "r"(b1));
}
__device__ __forceinline__ uint32_t smem_u32(const void* p) {
    uint32_t a;
    asm("{ .reg .u64 t; cvta.to.shared.u64 t, %1; cvt.u32.u64 %0, t; }" : "=r"(a) : "l"(p));
    return a;
}
__device__ __forceinline__ void cp16(uint32_t dst, const void* src) {
    asm volatile("cp.async.cg.shared.global [%0], [%1], 16;" :: "r"(dst), "l"(src) : "memory");
}
__device__ __forceinline__ uint32_t packh2(float lo, float hi) {
    uint32_t r;
    asm("cvt.rn.f16x2.f32 %0, %1, %2;" : "=r"(r) : "f"(hi), "f"(lo));
    return r;
}
__device__ __forceinline__ uint32_t prmt(uint32_t a, uint32_t b, uint32_t s) {
    uint32_t d;
    asm("prmt.b32 %0, %1, %2, %3;" : "=r"(d) : "r"(a), "r"(b), "r"(s));
    return d;
}

// ---------------- batched converts (R14 version) --------------------------------
__device__ __forceinline__ void conv_body(
    const float* __restrict__ in, __half2* __restrict__ out, int Rm, int isW)
{
    __shared__ float ts[128][33];
    const int m0 = blockIdx.x << 7, k0 = blockIdx.y << 5;
#pragma unroll
    for (int i = 0; i < 4; i++) {
        int idx = threadIdx.x + (i << 8);
        int ml = idx >> 3, kc = (idx & 7) << 2;
        float4 v = *(const float4*)(in + (size_t)(m0 + ml) * 1024 + k0 + kc);
        ts[ml][kc] = v.x; ts[ml][kc+1] = v.y; ts[ml][kc+2] = v.z; ts[ml][kc+3] = v.w;
    }
    __syncthreads();
#pragma unroll
    for (int i = 0; i < 8; i++) {
        int idx = threadIdx.x + (i << 8);
        int kp = idx >> 7, sc = idx & 127;
        int ml;
        if (isW) {
            int ch = sc >> 5, r = sc & 31, gg = (r >> 2) & 7, nt = r & 3;
            ml = ch * 32 + nt * 8 + gg;
        } else {
            int hf = sc >> 6, r = sc & 63, hi = (r >> 5) & 1, gg = (r >> 2) & 7, mt = r & 3;
            ml = hf * 64 + mt * 16 + hi * 8 + gg;
        }
        out[(size_t)((k0 >> 1) + kp) * Rm + m0 + sc] =
            __floats2half2_rn(ts[ml][2*kp], ts[ml][2*kp+1]);
    }
}
__global__ __launch_bounds__(256) void conv_w_all(Ptrs7 srcs, __half2* __restrict__ out) {
    conv_body(srcs.p[blockIdx.z], out + (size_t)blockIdx.z * WTS, DM, 1);
}
__global__ __launch_bounds__(256) void conv_a_all(Ptrs3 srcs, __half2* __restrict__ out) {
    conv_body(srcs.p[blockIdx.z], out + (size_t)blockIdx.z * ATS, MT, 0);
}

// ---------------- GEMM core (proven R9/R14 shape, coords as params) ------------
#define LDH 136
#define STG_H2 (32*LDH)
#define STG_BY (STG_H2*4)     // 17408 bytes
#define GSMEM (3*2*STG_BY)    // 104448

__device__ __forceinline__ void gemm_core(
    const __half2* __restrict__ At, const __half2* __restrict__ Wt,
    const float* __restrict__ bias, float* __restrict__ Cf, __half* __restrict__ Ch,
    __half2* smh, int bxn, int bym)
{
    const uint32_t sb = smem_u32(smh);
    const int tid = threadIdx.x, wid = tid >> 5, lane = tid & 31;
    const int g = lane >> 2, tig = lane & 3;
    const int wmh = (wid >> 1) * 64;
    const int wnc = (wid & 1) * 64;
    const int bm = bym << 7, bn = bxn << 7;

    float acc[4][8][4];
#pragma unroll
    for (int i = 0; i < 4; i++)
#pragma unroll
        for (int j = 0; j < 8; j++)
#pragma unroll
            for (int e = 0; e < 4; e++) acc[i][j][e] = 0.f;

#define LOAD_STAGE(J, S) do { \
    uint32_t dst = sb + (uint32_t)(S) * 2 * STG_BY; \
    _Pragma("unroll") \
    for (int p = 0; p < 8; p++) { \
        int ci = tid + (p << 7); \
        int row = ci >> 5, cc = ci & 31; \
        cp16(dst + row * (LDH*4) + cc * 16, \
             At + (size_t)((J) * 32 + row) * MT + bm + cc * 4); \
        cp16(dst + STG_BY + row * (LDH*4) + cc * 16, \
             Wt + (size_t)((J) * 32 + row) * DM + bn + cc * 4); \
    } \
    asm volatile("cp.async.commit_group;" ::: "memory"); \
} while (0)

    LOAD_STAGE(0, 0);
    LOAD_STAGE(1, 1);

    for (int j = 0; j < 16; j++) {
        if (j < 15) asm volatile("cp.async.wait_group 1;" ::: "memory");
        else        asm volatile("cp.async.wait_group 0;" ::: "memory");
        __syncthreads();

        const __half2* Ab = smh + (j % 3) * 2 * STG_H2;
        const __half2* Wb = Ab + STG_H2;
#pragma unroll
        for (int ks = 0; ks < 4; ks++) {
            const int kp0 = ks * 8 + tig;
            uint4 ua0 = *(const uint4*)&Ab[kp0*LDH     + wmh      + g*4];
            uint4 ua1 = *(const uint4*)&Ab[kp0*LDH     + wmh + 32 + g*4];
            uint4 ua2 = *(const uint4*)&Ab[(kp0+4)*LDH + wmh      + g*4];
            uint4 ua3 = *(const uint4*)&Ab[(kp0+4)*LDH + wmh + 32 + g*4];
            uint4 ub00 = *(const uint4*)&Wb[kp0*LDH     + wnc      + g*4];
            uint4 ub01 = *(const uint4*)&Wb[kp0*LDH     + wnc + 32 + g*4];
            uint4 ub10 = *(const uint4*)&Wb[(kp0+4)*LDH + wnc      + g*4];
            uint4 ub11 = *(const uint4*)&Wb[(kp0+4)*LDH + wnc + 32 + g*4];
            const uint32_t a0[4] = {ua0.x, ua0.y, ua0.z, ua0.w};
            const uint32_t a1[4] = {ua1.x, ua1.y, ua1.z, ua1.w};
            const uint32_t a2[4] = {ua2.x, ua2.y, ua2.z, ua2.w};
            const uint32_t a3[4] = {ua3.x, ua3.y, ua3.z, ua3.w};
            const uint32_t b0[8] = {ub00.x,ub00.y,ub00.z,ub00.w, ub01.x,ub01.y,ub01.z,ub01.w};
            const uint32_t b1[8] = {ub10.x,ub10.y,ub10.z,ub10.w, ub11.x,ub11.y,ub11.z,ub11.w};
#pragma unroll
            for (int mt = 0; mt < 4; mt++)
#pragma unroll
                for (int nt = 0; nt < 8; nt++)
                    mma16(acc[mt][nt], a0[mt], a1[mt], a2[mt], a3[mt],
                          b0[nt], b1[nt]);
        }
        if (j + 2 < 16) LOAD_STAGE(j + 2, (j + 2) % 3);
    }
#undef LOAD_STAGE

#pragma unroll
    for (int mt = 0; mt < 4; mt++) {
        int r0 = bm + (wid >> 1) * 64 + mt * 16 + g;
#pragma unroll
        for (int nt = 0; nt < 8; nt++) {
            int c = bn + (wid & 1) * 64 + (nt >> 2) * 32 + (nt & 3) * 8 + 2 * tig;
            float2 bv = *(const float2*)(bias + c);
            float o00 = acc[mt][nt][0] + bv.x, o01 = acc[mt][nt][1] + bv.y;
            float o10 = acc[mt][nt][2] + bv.x, o11 = acc[mt][nt][3] + bv.y;
            if (Ch) {
                *(uint32_t*)&Ch[(size_t)r0 * DM + c]       = packh2(o00, o01);
                *(uint32_t*)&Ch[(size_t)(r0 + 8) * DM + c] = packh2(o10, o11);
            } else {
                *(float2*)(Cf + (size_t)r0 * DM + c)       = make_float2(o00, o01);
                *(float2*)(Cf + (size_t)(r0 + 8) * DM + c) = make_float2(o10, o11);
            }
        }
    }
}

__global__ __launch_bounds__(128, 2) void gemm_fp16(
    const __half2* __restrict__ At, const __half2* __restrict__ Wt,
    const float* __restrict__ bias, float* __restrict__ Cf, __half* __restrict__ Ch)
{
    extern __shared__ __half2 smh[];
    gemm_core(At, Wt, bias, Cf, Ch, smh, blockIdx.x, blockIdx.y);
}

// ---------------- Flash attention core (R14 v8, coords as params) --------------
#define LDK2 88
#define ABUF (2*32*LDK2)      // half2 per stage buffer (Ks+Vs)
#define ASMEM (2*ABUF*4)      // 45056

__device__ __forceinline__ void attn_ldg(
    const __half* __restrict__ Kh, const __half* __restrict__ V,
    size_t base, int k0, int kkey, int kd0, int vkp, int vdg,
    uint32_t* kw, uint32_t* av, uint32_t* bv)
{
    const __half* kptr = Kh + base + (size_t)(k0 + kkey) * DM + kd0;
    uint4 u0 = *(const uint4*)kptr;
    uint4 u1 = *(const uint4*)(kptr + 8);
    uint4 u2 = *(const uint4*)(kptr + 16);
    uint4 u3 = *(const uint4*)(kptr + 24);
    kw[0]=u0.x; kw[1]=u0.y; kw[2]=u0.z; kw[3]=u0.w;
    kw[4]=u1.x; kw[5]=u1.y; kw[6]=u1.z; kw[7]=u1.w;
    kw[8]=u2.x; kw[9]=u2.y; kw[10]=u2.z; kw[11]=u2.w;
    kw[12]=u3.x; kw[13]=u3.y; kw[14]=u3.z; kw[15]=u3.w;
    const __half* v0 = V + base + (size_t)(k0 + 2*vkp) * DM + vdg;
    uint4 a  = *(const uint4*)v0;
    uint4 a2 = *(const uint4*)(v0 + 8);
    uint4 b  = *(const uint4*)(v0 + DM);
    uint4 b2 = *(const uint4*)(v0 + DM + 8);
    av[0]=a.x; av[1]=a.y; av[2]=a.z; av[3]=a.w;
    av[4]=a2.x; av[5]=a2.y; av[6]=a2.z; av[7]=a2.w;
    bv[0]=b.x; bv[1]=b.y; bv[2]=b.z; bv[3]=b.w;
    bv[4]=b2.x; bv[5]=b2.y; bv[6]=b2.z; bv[7]=b2.w;
}

__device__ __forceinline__ void attn_sts(
    __half2* Ks, __half2* Vs, int kc, int dp, int vkp, int vdg,
    const uint32_t* kw, const uint32_t* av, const uint32_t* bv)
{
#pragma unroll
    for (int i = 0; i < 16; i++)
        *(uint32_t*)&Ks[(dp + i)*LDK2 + kc] = kw[i];
    __half2* vrow = &Vs[vkp*LDK2];
#pragma unroll
    for (int e = 0; e < 8; e++) {
        int d0 = vdg + 2*e, d1 = d0 + 1;
        int c0 = (d0 & 7) * 8 + (d0 >> 3);
        int c1 = (d1 & 7) * 8 + (d1 >> 3);
        *(uint32_t*)&vrow[c0] = prmt(av[e], bv[e], 0x5410);
        *(uint32_t*)&vrow[c1] = prmt(av[e], bv[e], 0x7632);
    }
}

__device__ __forceinline__ void attn_core(
    const __half* __restrict__ Q, const __half* __restrict__ Kh,
    const __half* __restrict__ V, const __half* __restrict__ Vpost,
    __half* __restrict__ Oh, __half2* __restrict__ Oat,
    __half2* smh, int qx, int bh)
{
    const int tid = threadIdx.x, wid = tid >> 5, lane = tid & 31;
    const int g = lane >> 2, tig = lane & 3;
    const int wq = wid << 5;
    const int q0 = qx << 7;
    const int b = bh >> 4, h = bh & 15;
    const size_t base = (size_t)b * SS * DM + (size_t)h * DH;
    const float C = 0.125f * 1.44269504f;

    const int kkey = tid & 63, kd0 = (tid >> 6) << 5;
    const int kc = ((kkey & 7) << 3) | (kkey >> 3);
    const int dp = kd0 >> 1;
    const int vkp = tid >> 2, vdg = (tid & 3) << 4;

    uint32_t qa[2][4][4];
#pragma unroll
    for (int ms = 0; ms < 2; ms++) {
        const __half* qb = Q + base + (size_t)(q0 + wq + ms*16 + g) * DM;
#pragma unroll
        for (int ks = 0; ks < 4; ks++) {
            const int d0 = 2 * (ks * 8 + tig);
            qa[ms][ks][0] = *(const uint32_t*)(qb + d0);
            qa[ms][ks][1] = *(const uint32_t*)(qb + 8*DM + d0);
            qa[ms][ks][2] = *(const uint32_t*)(qb + d0 + 8);
            qa[ms][ks][3] = *(const uint32_t*)(qb + 8*DM + d0 + 8);
        }
    }

    float o[2][8][4];
#pragma unroll
    for (int ms = 0; ms < 2; ms++)
#pragma unroll
        for (int nt = 0; nt < 8; nt++)
#pragma unroll
            for (int e = 0; e < 4; e++) o[ms][nt][e] = 0.f;
    float mm[2][2], ll[2][2];
#pragma unroll
    for (int ms = 0; ms < 2; ms++) { mm[ms][0] = mm[ms][1] = -1e30f; ll[ms][0] = ll[ms][1] = 0.f; }

    uint32_t kw[16], av[8], bv[8];
    attn_ldg(Kh, V, base, 0, kkey, kd0, vkp, vdg, kw, av, bv);
    attn_sts(smh, smh + 32*LDK2, kc, dp, vkp, vdg, kw, av, bv);
    __syncthreads();

    for (int kt = 0; kt < 16; kt++) {
        const int cur = kt & 1;
        const __half2* Ks = smh + cur * ABUF;
        const __half2* Vs = Ks + 32*LDK2;

        if (kt < 15)
            attn_ldg(Kh, V, base, (kt + 1) << 6, kkey, kd0, vkp, vdg, kw, av, bv);

        float s[2][8][4];
#pragma unroll
        for (int ms = 0; ms < 2; ms++)
#pragma unroll
            for (int nt = 0; nt < 8; nt++)
#pragma unroll
                for (int e = 0; e < 4; e++) s[ms][nt][e] = 0.f;
#pragma unroll
        for (int ks = 0; ks < 4; ks++) {
            const int dp0 = ks * 8 + tig;
            uint4 u0 = *(const uint4*)&Ks[dp0*LDK2 + g*8];
            uint4 u1 = *(const uint4*)&Ks[dp0*LDK2 + g*8 + 4];
            uint4 u2 = *(const uint4*)&Ks[(dp0+4)*LDK2 + g*8];
            uint4 u3 = *(const uint4*)&Ks[(dp0+4)*LDK2 + g*8 + 4];
            const uint32_t b0[8] = {u0.x,u0.y,u0.z,u0.w, u1.x,u1.y,u1.z,u1.w};
            const uint32_t b1[8] = {u2.x,u2.y,u2.z,u2.w, u3.x,u3.y,u3.z,u3.w};
#pragma unroll
            for (int ms = 0; ms < 2; ms++)
#pragma unroll
                for (int nt = 0; nt < 8; nt++)
                    mma16(s[ms][nt], qa[ms][ks][0], qa[ms][ks][1],
                          qa[ms][ks][2], qa[ms][ks][3], b0[nt], b1[nt]);
        }

        uint32_t p[2][4][4];
        float al[2][2];
#pragma unroll
        for (int ms = 0; ms < 2; ms++) {
            float tm0 = -1e30f, tm1 = -1e30f;
#pragma unroll
            for (int nt = 0; nt < 8; nt++) {
                tm0 = fmaxf(tm0, fmaxf(s[ms][nt][0], s[ms][nt][1]));
                tm1 = fmaxf(tm1, fmaxf(s[ms][nt][2], s[ms][nt][3]));
            }
            tm0 = fmaxf(tm0, __shfl_xor_sync(0xffffffffu, tm0, 1));
            tm0 = fmaxf(tm0, __shfl_xor_sync(0xffffffffu, tm0, 2));
            tm1 = fmaxf(tm1, __shfl_xor_sync(0xffffffffu, tm1, 1));
            tm1 = fmaxf(tm1, __shfl_xor_sync(0xffffffffu, tm1, 2));
            float mn0 = fmaxf(mm[ms][0], tm0), mn1 = fmaxf(mm[ms][1], tm1);
            al[ms][0] = exp2f((mm[ms][0] - mn0) * C);
            al[ms][1] = exp2f((mm[ms][1] - mn1) * C);
            float rs0 = 0.f, rs1 = 0.f;
#pragma unroll
            for (int ks = 0; ks < 4; ks++) {
                float e00 = exp2f((s[ms][2*ks][0]   - mn0) * C), e01 = exp2f((s[ms][2*ks][1]   - mn0) * C);
                float e02 = exp2f((s[ms][2*ks][2]   - mn1) * C), e03 = exp2f((s[ms][2*ks][3]   - mn1) * C);
                float e10 = exp2f((s[ms][2*ks+1][0] - mn0) * C), e11 = exp2f((s[ms][2*ks+1][1] - mn0) * C);
                float e12 = exp2f((s[ms][2*ks+1][2] - mn1) * C), e13 = exp2f((s[ms][2*ks+1][3] - mn1) * C);
                rs0 += (e00 + e01) + (e10 + e11);
                rs1 += (e02 + e03) + (e12 + e13);
                p[ms][ks][0] = packh2(e00, e01);
                p[ms][ks][1] = packh2(e02, e03);
                p[ms][ks][2] = packh2(e10, e11);
                p[ms][ks][3] = packh2(e12, e13);
            }
            rs0 += __shfl_xor_sync(0xffffffffu, rs0, 1);
            rs0 += __shfl_xor_sync(0xffffffffu, rs0, 2);
            rs1 += __shfl_xor_sync(0xffffffffu, rs1, 1);
            rs1 += __shfl_xor_sync(0xffffffffu, rs1, 2);
            ll[ms][0] = ll[ms][0] * al[ms][0] + rs0;  mm[ms][0] = mn0;
            ll[ms][1] = ll[ms][1] * al[ms][1] + rs1;  mm[ms][1] = mn1;
        }

#pragma unroll
        for (int ms = 0; ms < 2; ms++)
#pragma unroll
            for (int nt = 0; nt < 8; nt++) {
                o[ms][nt][0] *= al[ms][0]; o[ms][nt][1] *= al[ms][0];
                o[ms][nt][2] *= al[ms][1]; o[ms][nt][3] *= al[ms][1];
            }
#pragma unroll
        for (int ks = 0; ks < 4; ks++) {
            const int kp0 = ks * 8 + tig;
            uint4 u0 = *(const uint4*)&Vs[kp0*LDK2 + g*8];
            uint4 u1 = *(const uint4*)&Vs[kp0*LDK2 + g*8 + 4];
            uint4 u2 = *(const uint4*)&Vs[(kp0+4)*LDK2 + g*8];
            uint4 u3 = *(const uint4*)&Vs[(kp0+4)*LDK2 + g*8 + 4];
            const uint32_t b0[8] = {u0.x,u0.y,u0.z,u0.w, u1.x,u1.y,u1.z,u1.w};
            const uint32_t b1[8] = {u2.x,u2.y,u2.z,u2.w, u3.x,u3.y,u3.z,u3.w};
#pragma unroll
            for (int ms = 0; ms < 2; ms++)
#pragma unroll
                for (int nt = 0; nt < 8; nt++)
                    mma16(o[ms][nt], p[ms][ks][0], p[ms][ks][1],
                          p[ms][ks][2], p[ms][ks][3], b0[nt], b1[nt]);
        }

        if (kt < 15) {
            __half2* KsN = smh + (cur ^ 1) * ABUF;
            attn_sts(KsN, KsN + 32*LDK2, kc, dp, vkp, vdg, kw, av, bv);
        }
        __syncthreads();
    }

#pragma unroll
    for (int ms = 0; ms < 2; ms++) {
        float il0 = 1.f / ll[ms][0], il1 = 1.f / ll[ms][1];
        const int r = q0 + wq + ms*16 + g;
        if (Oh) {
#pragma unroll
            for (int nt = 0; nt < 8; nt++) {
                int d0 = nt * 8 + 2 * tig;
                float o00 = o[ms][nt][0]*il0, o01 = o[ms][nt][1]*il0;
                float o10 = o[ms][nt][2]*il1, o11 = o[ms][nt][3]*il1;
                if (Vpost) {
                    uint32_t v0 = *(const uint32_t*)(Vpost + base + (size_t)r * DM + d0);
                    uint32_t v1 = *(const uint32_t*)(Vpost + base + (size_t)(r+8) * DM + d0);
                    float2 f0 = __half22float2(*(__half2*)&v0);
                    float2 f1 = __half22float2(*(__half2*)&v1);
                    o00 += f0.x; o01 += f0.y; o10 += f1.x; o11 += f1.y;
                }
                *(uint32_t*)&Oh[base + (size_t)r * DM + d0]     = packh2(o00, o01);
                *(uint32_t*)&Oh[base + (size_t)(r+8) * DM + d0] = packh2(o10, o11);
            }
        } else {
            const size_t mbase = (size_t)b * SS + q0;
            const int lq = wq + ms*16 + g;
            const int mp0 = ((lq >> 6) & 1) * 64 + ((lq >> 3) & 1) * 32 + (lq & 7) * 4 + ((lq >> 4) & 3);
            const int lq1 = lq + 8;
            const int mp1 = ((lq1 >> 6) & 1) * 64 + ((lq1 >> 3) & 1) * 32 + (lq1 & 7) * 4 + ((lq1 >> 4) & 3);
#pragma unroll
            for (int nt = 0; nt < 8; nt++) {
                const int kp = h * 32 + nt * 4 + tig;
                *(uint32_t*)&Oat[(size_t)kp * MT + mbase + mp0] =
                    packh2(o[ms][nt][0]*il0, o[ms][nt][1]*il0);
                *(uint32_t*)&Oat[(size_t)kp * MT + mbase + mp1] =
                    packh2(o[ms][nt][2]*il1, o[ms][nt][3]*il1);
            }
        }
    }
}

__global__ __launch_bounds__(128, 2) void attn_h(
    const __half* __restrict__ Q, const __half* __restrict__ Kh,
    const __half* __restrict__ V, const __half* __restrict__ Vpost,
    __half* __restrict__ Oh, __half2* __restrict__ Oat)
{
    extern __shared__ __half2 smh[];
    attn_core(Q, Kh, V, Vpost, Oh, Oat, smh, blockIdx.x, blockIdx.y);
}

// ---------------- fused: attn#1 (512 CTAs) + gq GEMM (256) + gk GEMM (256) -----
__global__ __launch_bounds__(128, 2) void fused_ag(
    const __half* __restrict__ pqh, const __half* __restrict__ pkh,
    const __half* __restrict__ pvh, const __half* __restrict__ vh,
    __half* __restrict__ a2h,
    const __half2* __restrict__ atG, const __half2* __restrict__ atL,
    const __half2* __restrict__ wts,
    const float* __restrict__ gqb, const float* __restrict__ gkb,
    __half* __restrict__ qh, __half* __restrict__ kh)
{
    extern __shared__ __half2 smh[];
    const int bx = blockIdx.x;
    if (bx < 512) {
        // attn#1: att2+gv = softmax(pq pk^T/8) @ pv + gv
        attn_core(pqh, pkh, pvh, vh, a2h, nullptr, smh, bx & 7, bx >> 3);
    } else if (bx < 768) {
        const int r = bx - 512;
        gemm_core(atG, wts, gqb, nullptr, qh, smh, r & 7, r >> 3);
    } else {
        const int r = bx - 768;
        gemm_core(atL, wts + WTS, gkb, nullptr, kh, smh, r & 7, r >> 3);
    }
}

// ---------------- launch --------------------------------------------------------
extern "C" void kernel_launch(void* const* d_in, const int* in_sizes, int n_in,
                              void* d_out, int out_size) {
    (void)in_sizes; (void)n_in; (void)out_size;
    const float* gfeat = (const float*)d_in[0];
    const float* lfeat = (const float*)d_in[1];
    const float* tfeat = (const float*)d_in[2];
    const float* gqw = (const float*)d_in[3];  const float* gqb = (const float*)d_in[4];
    const float* gkw = (const float*)d_in[5];  const float* gkb = (const float*)d_in[6];
    const float* gvw = (const float*)d_in[7];  const float* gvb = (const float*)d_in[8];
    const float* pqw = (const float*)d_in[9];  const float* pqb = (const float*)d_in[10];
    const float* pkw = (const float*)d_in[11]; const float* pkb = (const float*)d_in[12];
    const float* pvw = (const float*)d_in[13]; const float* pvb = (const float*)d_in[14];
    const float* dw  = (const float*)d_in[15]; const float* db  = (const float*)d_in[16];
    float* out = (float*)d_out;

    __half2 *acts, *wts, *ctxat;
    __half *proj, *a2h;
    cudaGetSymbolAddress((void**)&acts,  g_acts);
    cudaGetSymbolAddress((void**)&wts,   g_wts);
    cudaGetSymbolAddress((void**)&proj,  g_proj);
    cudaGetSymbolAddress((void**)&a2h,   g_a2h);
    cudaGetSymbolAddress((void**)&ctxat, g_ctxat);

    __half* qh  = proj;
    __half* kh  = proj + 1*(size_t)MT*DM;
    __half* vh  = proj + 2*(size_t)MT*DM;
    __half* pqh = proj + 3*(size_t)MT*DM;
    __half* pkh = proj + 4*(size_t)MT*DM;
    __half* pvh = proj + 5*(size_t)MT*DM;

    cudaFuncSetAttribute(gemm_fp16, cudaFuncAttributeMaxDynamicSharedMemorySize, GSMEM);
    cudaFuncSetAttribute(attn_h,    cudaFuncAttributeMaxDynamicSharedMemorySize, ASMEM);
    cudaFuncSetAttribute(fused_ag,  cudaFuncAttributeMaxDynamicSharedMemorySize, GSMEM);

    dim3 gg(DM/128, MT/128);          // (8, 32)
    dim3 ga(SS/128, BB*NH);           // (8, 64)
    dim3 gcw(DM/128, DM/32, 7);
    dim3 gca(MT/128, DM/32, 3);

    Ptrs7 wp = {{ gqw, gkw, gvw, pqw, pkw, pvw, dw }};
    Ptrs3 ap = {{ gfeat, lfeat, tfeat }};
    conv_w_all<<<gcw, 256>>>(wp, wts);
    conv_a_all<<<gca, 256>>>(ap, acts);

    const __half2* atG = acts;
    const __half2* atL = acts + ATS;
    const __half2* atT = acts + 2*ATS;

    // projections needed by attn#1 first
#define GEMMH(A, wi, bias, dst) gemm_fp16<<<gg, 128, GSMEM>>>((A), wts + (wi)*(size_t)WTS, (bias), nullptr, (dst))
    GEMMH(atL, 2, gvb, vh);
    GEMMH(atL, 3, pqb, pqh);
    GEMMH(atT, 4, pkb, pkh);
    GEMMH(atT, 5, pvb, pvh);
#undef GEMMH

    // fused: attn#1 runs concurrently with the gq / gk projections
    fused_ag<<<1024, 128, GSMEM>>>(pqh, pkh, pvh, vh, a2h,
                                   atG, atL, wts, gqb, gkb, qh, kh);

    // ctx = softmax(gq gk^T/8) @ (att2+gv) -> permuted at-layout
    attn_h<<<ga, 128, ASMEM>>>(qh, kh, a2h, nullptr, nullptr, ctxat);

    // dense: fp32 out
    gemm_fp16<<<gg, 128, GSMEM>>>(ctxat, wts + 6*(size_t)WTS, db, out, nullptr);
}